// round 11
// baseline (speedup 1.0000x reference)
#include <cuda_runtime.h>

// RoIBridge round 11: software-pipelined grid-stride loop.
// R8-R10 plateau at ~4.45TB/s with nothing saturated -> exposed per-iteration
// latency (LDG -> branch -> LDS -> STG serialized). Fixes:
//  - prefetch next iteration's obj/frac4 before processing current one
//  - unconditional LDS gathers; mask applied as x{0,1} multiply at store time
//    (obj load no longer heads the critical path)
//  - same shell: 57.6KB smem table, 456 blocks x 512 thr, 3 blocks/SM

static constexpr int IMAGE_SIZE = 224;
static constexpr int ROWS = 2048 * 128;       // 262144
static constexpr int TABLE_F4 = 225 * 16;     // 3600 float4 = 57600 B
static constexpr int PAIRS = ROWS / 2;        // 131072

__device__ __forceinline__ int clamp_idx(float f) {
    float x = fminf(fmaxf(f * (float)IMAGE_SIZE, 0.0f), (float)IMAGE_SIZE);
    return (int)x;   // trunc toward zero == astype(int32), x >= 0
}

__device__ __forceinline__ float4 scale4(float4 v, float s) {
    return make_float4(v.x * s, v.y * s, v.z * s, v.w * s);
}

extern __shared__ float4 s_tab[];             // [225*16]

__global__ void __launch_bounds__(512, 3)
roibridge_kernel(const float4* __restrict__ frac4,   // [ROWS]
                 const int*    __restrict__ obj,     // [ROWS]
                 const float4* __restrict__ table4,  // [225*16]
                 float4*       __restrict__ out)     // [ROWS*64]
{
    // ---- stage table into shared memory (one-time per block) ----
    for (int i = threadIdx.x; i < TABLE_F4; i += blockDim.x)
        s_tab[i] = table4[i];
    __syncthreads();

    const int tid     = blockIdx.x * blockDim.x + threadIdx.x;
    const int d4      = tid & 15;                        // loop-invariant lane
    const int pstride = (gridDim.x * blockDim.x) >> 4;   // 14592 pairs/step
    int p = tid >> 4;

    const float4 z = make_float4(0.f, 0.f, 0.f, 0.f);

    // prologue: total threads (233472) < PAIRS*16, so first item always valid
    int    o0 = __ldg(obj   + 2 * p);
    int    o1 = __ldg(obj   + 2 * p + 1);
    float4 f0 = __ldg(frac4 + 2 * p);
    float4 f1 = __ldg(frac4 + 2 * p + 1);

    while (true) {
        // ---- prefetch next iteration's scalars (overlaps this iteration) ----
        const int pn = p + pstride;
        int o0n = 0, o1n = 0;
        float4 f0n = z, f1n = z;
        if (pn < PAIRS) {
            o0n = __ldg(obj   + 2 * pn);
            o1n = __ldg(obj   + 2 * pn + 1);
            f0n = __ldg(frac4 + 2 * pn);
            f1n = __ldg(frac4 + 2 * pn + 1);
        }

        // ---- row 2p: unconditional gathers, masked via multiply ----
        {
            float4 a0 = s_tab[clamp_idx(f0.x) * 16 + d4];
            float4 a1 = s_tab[clamp_idx(f0.y) * 16 + d4];
            float4 a2 = s_tab[clamp_idx(f0.z) * 16 + d4];
            float4 a3 = s_tab[clamp_idx(f0.w) * 16 + d4];
            float  m  = (o0 == 1) ? 1.0f : 0.0f;   // table is finite: v*0 == 0
            float4* q = out + (2 * p) * 64 + d4;
            __stcs(q +  0, scale4(a0, m));
            __stcs(q + 16, scale4(a1, m));
            __stcs(q + 32, scale4(a2, m));
            __stcs(q + 48, scale4(a3, m));
        }

        // ---- row 2p+1 ----
        {
            float4 b0 = s_tab[clamp_idx(f1.x) * 16 + d4];
            float4 b1 = s_tab[clamp_idx(f1.y) * 16 + d4];
            float4 b2 = s_tab[clamp_idx(f1.z) * 16 + d4];
            float4 b3 = s_tab[clamp_idx(f1.w) * 16 + d4];
            float  m  = (o1 == 1) ? 1.0f : 0.0f;
            float4* q = out + (2 * p + 1) * 64 + d4;
            __stcs(q +  0, scale4(b0, m));
            __stcs(q + 16, scale4(b1, m));
            __stcs(q + 32, scale4(b2, m));
            __stcs(q + 48, scale4(b3, m));
        }

        if (pn >= PAIRS) break;
        p = pn; o0 = o0n; o1 = o1n; f0 = f0n; f1 = f1n;
    }
}

extern "C" void kernel_launch(void* const* d_in, const int* in_sizes, int n_in,
                              void* d_out, int out_size)
{
    const float4* frac4 = (const float4*)d_in[0];   // [2048,128,4] f32
    const int*    obj   = (const int*)d_in[1];      // [2048,128] i32
    const float4* table = (const float4*)d_in[2];   // [225,64] f32
    float4* out = (float4*)d_out;

    const int smem_bytes = TABLE_F4 * sizeof(float4);   // 57600
    cudaFuncSetAttribute(roibridge_kernel,
                         cudaFuncAttributeMaxDynamicSharedMemorySize, smem_bytes);

    const int threads = 512;
    const int blocks = 152 * 3;   // 152 SMs, 3 blocks/SM

    roibridge_kernel<<<blocks, threads, smem_bytes>>>(frac4, obj, table, out);
}

// round 12
// speedup vs baseline: 1.3173x; 1.3173x over previous
#include <cuda_runtime.h>

// RoIBridge round 12: R10 body (conditional gathers — half the rows are
// masked, skipping their LDS traffic matters) + R11's scalar prefetch
// pipeline (next iteration's obj/frac LDGs overlap current gather/store).
// R11's mistake (unconditional gathers + mask-multiply) is reverted: it
// doubled LDS traffic and re-created the L1TEX wall.
//  - 57.6KB smem table, 456 blocks x 512 thr, 3 blocks/SM
//  - per pair: 4 front-batched independent LDGs (prefetched), 8 conditional
//    conflict-free LDS.128 gathers, 8 coalesced __stcs stores

static constexpr int IMAGE_SIZE = 224;
static constexpr int ROWS = 2048 * 128;       // 262144
static constexpr int TABLE_F4 = 225 * 16;     // 3600 float4 = 57600 B
static constexpr int PAIRS = ROWS / 2;        // 131072

__device__ __forceinline__ int clamp_idx(float f) {
    float x = fminf(fmaxf(f * (float)IMAGE_SIZE, 0.0f), (float)IMAGE_SIZE);
    return (int)x;   // trunc toward zero == astype(int32), x >= 0
}

extern __shared__ float4 s_tab[];             // [225*16]

__global__ void __launch_bounds__(512, 3)
roibridge_kernel(const float4* __restrict__ frac4,   // [ROWS]
                 const int*    __restrict__ obj,     // [ROWS]
                 const float4* __restrict__ table4,  // [225*16]
                 float4*       __restrict__ out)     // [ROWS*64]
{
    // ---- stage table into shared memory (one-time per block) ----
    for (int i = threadIdx.x; i < TABLE_F4; i += blockDim.x)
        s_tab[i] = table4[i];
    __syncthreads();

    const int tid     = blockIdx.x * blockDim.x + threadIdx.x;
    const int d4      = tid & 15;                        // loop-invariant lane
    const int pstride = (gridDim.x * blockDim.x) >> 4;   // 14592 pairs/step
    int p = tid >> 4;

    const float4 z = make_float4(0.f, 0.f, 0.f, 0.f);

    // prologue (233472 threads < PAIRS*16 -> first item always valid)
    int    o0 = __ldg(obj   + 2 * p);
    int    o1 = __ldg(obj   + 2 * p + 1);
    float4 f0 = __ldg(frac4 + 2 * p);
    float4 f1 = __ldg(frac4 + 2 * p + 1);

    while (true) {
        // ---- prefetch next iteration's scalars (overlap with below) ----
        const int pn = p + pstride;
        int o0n = 0, o1n = 0;
        float4 f0n = z, f1n = z;
        if (pn < PAIRS) {
            o0n = __ldg(obj   + 2 * pn);
            o1n = __ldg(obj   + 2 * pn + 1);
            f0n = __ldg(frac4 + 2 * pn);
            f1n = __ldg(frac4 + 2 * pn + 1);
        }

        // ---- row 2p: conditional gathers (skip LDS for masked rows) ----
        {
            float4 a0 = z, a1 = z, a2 = z, a3 = z;
            if (o0 == 1) {
                a0 = s_tab[clamp_idx(f0.x) * 16 + d4];
                a1 = s_tab[clamp_idx(f0.y) * 16 + d4];
                a2 = s_tab[clamp_idx(f0.z) * 16 + d4];
                a3 = s_tab[clamp_idx(f0.w) * 16 + d4];
            }
            float4* q = out + (2 * p) * 64 + d4;
            __stcs(q +  0, a0);
            __stcs(q + 16, a1);
            __stcs(q + 32, a2);
            __stcs(q + 48, a3);
        }

        // ---- row 2p+1 ----
        {
            float4 b0 = z, b1 = z, b2 = z, b3 = z;
            if (o1 == 1) {
                b0 = s_tab[clamp_idx(f1.x) * 16 + d4];
                b1 = s_tab[clamp_idx(f1.y) * 16 + d4];
                b2 = s_tab[clamp_idx(f1.z) * 16 + d4];
                b3 = s_tab[clamp_idx(f1.w) * 16 + d4];
            }
            float4* q = out + (2 * p + 1) * 64 + d4;
            __stcs(q +  0, b0);
            __stcs(q + 16, b1);
            __stcs(q + 32, b2);
            __stcs(q + 48, b3);
        }

        if (pn >= PAIRS) break;
        p = pn; o0 = o0n; o1 = o1n; f0 = f0n; f1 = f1n;
    }
}

extern "C" void kernel_launch(void* const* d_in, const int* in_sizes, int n_in,
                              void* d_out, int out_size)
{
    const float4* frac4 = (const float4*)d_in[0];   // [2048,128,4] f32
    const int*    obj   = (const int*)d_in[1];      // [2048,128] i32
    const float4* table = (const float4*)d_in[2];   // [225,64] f32
    float4* out = (float4*)d_out;

    const int smem_bytes = TABLE_F4 * sizeof(float4);   // 57600
    cudaFuncSetAttribute(roibridge_kernel,
                         cudaFuncAttributeMaxDynamicSharedMemorySize, smem_bytes);

    const int threads = 512;
    const int blocks = 152 * 3;   // 152 SMs, 3 blocks/SM

    roibridge_kernel<<<blocks, threads, smem_bytes>>>(frac4, obj, table, out);
}